// round 3
// baseline (speedup 1.0000x reference)
#include <cuda_runtime.h>
#include <cuda_bf16.h>

// LSTM: B=4096, T=200, IN=2, H=64, gates=256 (i,f,g,o torch order)
// out[b] = dot(h_last[b], W_fc) + b_fc
//
// Design: 147 CTAs x 256 threads; each CTA owns 28 batch rows for all 200
// steps (batch is fully parallel -> no inter-CTA sync). Thread t holds W_hh
// row t in registers as pre-duplicated f32x2 pairs. h state lives in smem
// interleaved as (b,b+1) float2 so LDS.128 yields two f32x2 operands
// directly. Phase 2 does activations with ex2/rcp.approx; c stays in regs.

#define B_TOT   4096
#define T_LEN   200
#define H_DIM   64
#define G_DIM   256           // 4*H
#define BR      28            // batch rows per CTA
#define PAIRS   14            // BR/2
#define NTHR    256

// smem float offsets
#define XS_OFF   0                        // [200][14][4] = 11200 floats
#define XS_SZ    (T_LEN * PAIRS * 4)
#define GS_OFF   (XS_OFF + XS_SZ)         // [28][256] = 7168 floats
#define GS_SZ    (BR * G_DIM)
#define HS_OFF   (GS_OFF + GS_SZ)         // [14][64] float2 = 1792 floats
#define HS_SZ    (PAIRS * H_DIM * 2)
#define SMEM_FLOATS (XS_OFF + XS_SZ + GS_SZ + HS_SZ)
#define SMEM_BYTES  (SMEM_FLOATS * 4)

__device__ __forceinline__ unsigned long long pack2(float a, float b) {
    unsigned long long r;
    asm("mov.b64 %0, {%1, %2};" : "=l"(r) : "f"(a), "f"(b));
    return r;
}
__device__ __forceinline__ void unpack2(unsigned long long v, float& a, float& b) {
    asm("mov.b64 {%0, %1}, %2;" : "=f"(a), "=f"(b) : "l"(v));
}
__device__ __forceinline__ unsigned long long fma2(unsigned long long a,
                                                   unsigned long long b,
                                                   unsigned long long c) {
    unsigned long long d;
    asm("fma.rn.f32x2 %0, %1, %2, %3;" : "=l"(d) : "l"(a), "l"(b), "l"(c));
    return d;
}
__device__ __forceinline__ unsigned long long add2(unsigned long long a,
                                                   unsigned long long b) {
    unsigned long long d;
    asm("add.rn.f32x2 %0, %1, %2;" : "=l"(d) : "l"(a), "l"(b));
    return d;
}

__device__ __forceinline__ float ex2f(float x) {
    float r; asm("ex2.approx.f32 %0, %1;" : "=f"(r) : "f"(x)); return r;
}
__device__ __forceinline__ float rcpf(float x) {
    float r; asm("rcp.approx.f32 %0, %1;" : "=f"(r) : "f"(x)); return r;
}
// sigmoid(x) = 1/(1+exp(-x)) = 1/(1+2^(-x*log2e))
__device__ __forceinline__ float sigf(float x) {
    float e = ex2f(-1.4426950408889634f * x);
    return rcpf(1.0f + e);
}
// tanh(x) = 2/(1+exp(-2x)) - 1
__device__ __forceinline__ float tanhf_(float x) {
    float e = ex2f(-2.8853900817779268f * x);
    return fmaf(2.0f, rcpf(1.0f + e), -1.0f);
}

__global__ __launch_bounds__(NTHR, 1)
void lstm_kernel(const float* __restrict__ x,
                 const float* __restrict__ W_ih,
                 const float* __restrict__ W_hh,
                 const float* __restrict__ b_ih,
                 const float* __restrict__ b_hh,
                 const float* __restrict__ W_fc,
                 const float* __restrict__ b_fc,
                 float* __restrict__ out) {
    extern __shared__ float sm[];
    float* xs  = sm + XS_OFF;   // x staged, layout [t][pair][x0_b,x0_b1,x1_b,x1_b1]
    float* gsm = sm + GS_OFF;   // gates [b][256]
    float* hsm = sm + HS_OFF;   // h as float2 (b even, b odd) x [k]

    const int tid  = threadIdx.x;
    const int base = blockIdx.x * BR;

    // ---- W_hh row for gate g = tid, duplicated into f32x2 pairs (regs) ----
    unsigned long long wp[H_DIM];
    #pragma unroll
    for (int k = 0; k < H_DIM; k++) {
        float v = W_hh[tid * H_DIM + k];
        wp[k] = pack2(v, v);
    }
    const float wih0 = W_ih[tid * 2 + 0];
    const float wih1 = W_ih[tid * 2 + 1];
    const float bias = b_ih[tid] + b_hh[tid];
    const unsigned long long wih0p = pack2(wih0, wih0);
    const unsigned long long wih1p = pack2(wih1, wih1);
    const unsigned long long bias2 = pack2(bias, bias);
    const unsigned long long zero2 = pack2(0.0f, 0.0f);

    // ---- final-projection weights hoisted (used after the time loop) ----
    const float wfc = (tid < H_DIM) ? W_fc[tid] : 0.0f;
    const float bfc = b_fc[0];

    // ---- zero h state ----
    for (int i = tid; i < HS_SZ; i += NTHR) hsm[i] = 0.0f;

    // ---- stage x: 28 rows x 200 steps x 2 ch -> pair-interleaved layout ----
    for (int id = tid; id < BR * T_LEN * 2; id += NTHR) {
        int row = id / (T_LEN * 2);
        int rem = id - row * (T_LEN * 2);
        int t   = rem >> 1;
        int c   = rem & 1;
        int gb  = base + row;
        float v = (gb < B_TOT) ? x[gb * (T_LEN * 2) + rem] : 0.0f;
        xs[(t * PAIRS + (row >> 1)) * 4 + c * 2 + (row & 1)] = v;
    }

    float c_state[7];
    #pragma unroll
    for (int s = 0; s < 7; s++) c_state[s] = 0.0f;

    __syncthreads();

    const ulonglong2* hp = (const ulonglong2*)hsm;

    for (int t = 0; t < T_LEN; t++) {
        // ---- phase 1: thread t computes gate row t for all 28 batch rows ----
        const ulonglong2* xp = (const ulonglong2*)(xs + t * PAIRS * 4);
        #pragma unroll
        for (int p = 0; p < PAIRS; p++) {
            ulonglong2 xv = xp[p];   // .x=(x0_b,x0_b1) .y=(x1_b,x1_b1)
            unsigned long long acc0 = fma2(xv.x, wih0p, bias2);
            unsigned long long acc1 = fma2(xv.y, wih1p, zero2);
            #pragma unroll
            for (int kk = 0; kk < H_DIM / 2; kk++) {
                ulonglong2 hv = hp[p * (H_DIM / 2) + kk]; // .x=h pair @k, .y=@k+1
                acc0 = fma2(hv.x, wp[2 * kk + 0], acc0);
                acc1 = fma2(hv.y, wp[2 * kk + 1], acc1);
            }
            float ga, gb2;
            unpack2(add2(acc0, acc1), ga, gb2);
            gsm[(2 * p + 0) * G_DIM + tid] = ga;
            gsm[(2 * p + 1) * G_DIM + tid] = gb2;
        }
        __syncthreads();

        // ---- phase 2: state update, 7 (b,j) items per thread ----
        #pragma unroll
        for (int s = 0; s < 7; s++) {
            int idx = tid + NTHR * s;
            int b = idx >> 6;
            int j = idx & 63;
            const float* gr = gsm + b * G_DIM + j;
            float gi = gr[0];
            float gf = gr[64];
            float gg = gr[128];
            float go = gr[192];
            float i_ = sigf(gi);
            float f_ = sigf(gf);
            float g_ = tanhf_(gg);
            float o_ = sigf(go);
            float c = f_ * c_state[s] + i_ * g_;
            c_state[s] = c;
            float h = o_ * tanhf_(c);
            hsm[((b >> 1) * H_DIM + j) * 2 + (b & 1)] = h;
        }
        __syncthreads();
    }

    // ---- final projection: out[b] = dot(h_last, W_fc) + b_fc ----
    if (tid < H_DIM) gsm[tid] = wfc;   // stage W_fc row into smem once
    __syncthreads();
    if (tid < BR) {
        int gb = base + tid;
        if (gb < B_TOT) {
            float acc = 0.0f;
            #pragma unroll
            for (int j = 0; j < H_DIM; j++) {
                float h = hsm[((tid >> 1) * H_DIM + j) * 2 + (tid & 1)];
                acc += h * gsm[j];
            }
            out[gb] = acc + bfc;
        }
    }
}

extern "C" void kernel_launch(void* const* d_in, const int* in_sizes, int n_in,
                              void* d_out, int out_size) {
    const float* x    = (const float*)d_in[0];
    const float* W_ih = (const float*)d_in[1];
    const float* W_hh = (const float*)d_in[2];
    const float* b_ih = (const float*)d_in[3];
    const float* b_hh = (const float*)d_in[4];
    const float* W_fc = (const float*)d_in[5];
    const float* b_fc = (const float*)d_in[6];
    float* out = (float*)d_out;

    cudaFuncSetAttribute(lstm_kernel,
                         cudaFuncAttributeMaxDynamicSharedMemorySize,
                         SMEM_BYTES);

    int grid = (B_TOT + BR - 1) / BR;  // 147
    lstm_kernel<<<grid, NTHR, SMEM_BYTES>>>(x, W_ih, W_hh, b_ih, b_hh,
                                            W_fc, b_fc, out);
}

// round 10
// speedup vs baseline: 1.2665x; 1.2665x over previous
#include <cuda_runtime.h>
#include <cuda_bf16.h>

// LSTM: B=4096, T=200, IN=2, H=64, gates=256 (i,f,g,o torch order)
// out[b] = dot(h_last[b], W_fc) + b_fc
//
// R4 design (from R3 ncu: L1/shared 78.5% = bottleneck, fma 41.4%):
// each thread owns TWO gate rows (k-packed f32x2 weights, 128 regs) and
// half the batch rows, so one LDS.128 of h[b][k..k+3] feeds 4 FFMA2 instead
// of 2. Halves shared-memory wavefronts; FMA pipe becomes the binder.
// h is plain [28][64] row-major; all phase-1 smem loads are warp-uniform
// broadcasts.

#define B_TOT   4096
#define T_LEN   200
#define H_DIM   64
#define G_DIM   256           // 4*H
#define BR      28            // batch rows per CTA
#define HB      14            // batch rows per thread-half
#define NTHR    256

// smem float offsets: hsm | gsm | xs
#define HS_OFF   0
#define HS_SZ    (BR * H_DIM)             // 1792 floats
#define GS_OFF   (HS_OFF + HS_SZ)
#define GS_SZ    (BR * G_DIM)             // 7168 floats
#define XS_OFF   (GS_OFF + GS_SZ)         // float2[t][b] = x0,x1
#define XS_SZ    (T_LEN * BR * 2)         // 11200 floats
#define SMEM_FLOATS (XS_OFF + XS_SZ)
#define SMEM_BYTES  (SMEM_FLOATS * 4)

__device__ __forceinline__ unsigned long long pack2(float a, float b) {
    unsigned long long r;
    asm("mov.b64 %0, {%1, %2};" : "=l"(r) : "f"(a), "f"(b));
    return r;
}
__device__ __forceinline__ void unpack2(unsigned long long v, float& a, float& b) {
    asm("mov.b64 {%0, %1}, %2;" : "=f"(a), "=f"(b) : "l"(v));
}
__device__ __forceinline__ unsigned long long fma2(unsigned long long a,
                                                   unsigned long long b,
                                                   unsigned long long c) {
    unsigned long long d;
    asm("fma.rn.f32x2 %0, %1, %2, %3;" : "=l"(d) : "l"(a), "l"(b), "l"(c));
    return d;
}
__device__ __forceinline__ unsigned long long add2(unsigned long long a,
                                                   unsigned long long b) {
    unsigned long long d;
    asm("add.rn.f32x2 %0, %1, %2;" : "=l"(d) : "l"(a), "l"(b));
    return d;
}

__device__ __forceinline__ float ex2f(float x) {
    float r; asm("ex2.approx.f32 %0, %1;" : "=f"(r) : "f"(x)); return r;
}
__device__ __forceinline__ float rcpf(float x) {
    float r; asm("rcp.approx.f32 %0, %1;" : "=f"(r) : "f"(x)); return r;
}
__device__ __forceinline__ float sigf(float x) {
    float e = ex2f(-1.4426950408889634f * x);
    return rcpf(1.0f + e);
}
__device__ __forceinline__ float tanhf_(float x) {
    float e = ex2f(-2.8853900817779268f * x);
    return fmaf(2.0f, rcpf(1.0f + e), -1.0f);
}

__global__ __launch_bounds__(NTHR, 1)
void lstm_kernel(const float* __restrict__ x,
                 const float* __restrict__ W_ih,
                 const float* __restrict__ W_hh,
                 const float* __restrict__ b_ih,
                 const float* __restrict__ b_hh,
                 const float* __restrict__ W_fc,
                 const float* __restrict__ b_fc,
                 float* __restrict__ out) {
    extern __shared__ float sm[];
    float*  hsm = sm + HS_OFF;            // [28][64]
    float*  gsm = sm + GS_OFF;            // [28][256]
    float2* xsf = (float2*)(sm + XS_OFF); // [200][28]

    const int tid = threadIdx.x;
    const int gp  = tid & 127;            // gate pair index 0..127
    const int s   = tid >> 7;             // batch half 0/1
    const int g0  = 2 * gp;
    const int g1  = 2 * gp + 1;
    const int bs  = s * HB;               // batch row start for this thread
    const int base = blockIdx.x * BR;

    // ---- weights for 2 gate rows, k-packed f32x2 (64+64 = 128 regs) ----
    unsigned long long w0[H_DIM / 2], w1[H_DIM / 2];
    {
        const float2* wr0 = (const float2*)(W_hh + g0 * H_DIM);
        const float2* wr1 = (const float2*)(W_hh + g1 * H_DIM);
        #pragma unroll
        for (int m = 0; m < H_DIM / 2; m++) {
            float2 a = wr0[m]; w0[m] = pack2(a.x, a.y);
            float2 b = wr1[m]; w1[m] = pack2(b.x, b.y);
        }
    }
    const float wA0 = W_ih[g0 * 2 + 0], wA1 = W_ih[g0 * 2 + 1];
    const float wB0 = W_ih[g1 * 2 + 0], wB1 = W_ih[g1 * 2 + 1];
    const float bias0 = b_ih[g0] + b_hh[g0];
    const float bias1 = b_ih[g1] + b_hh[g1];

    const float wfc = (tid < H_DIM) ? W_fc[tid] : 0.0f;
    const float bfc = b_fc[0];

    // ---- zero h state ----
    for (int i = tid; i < HS_SZ; i += NTHR) hsm[i] = 0.0f;

    // ---- stage x: [t][b] -> float2(x0,x1); one-time, tiny ----
    for (int id = tid; id < T_LEN * BR; id += NTHR) {
        int t = id / BR;
        int b = id - t * BR;
        int gb = base + b;
        float2 v = make_float2(0.0f, 0.0f);
        if (gb < B_TOT) v = *(const float2*)(x + gb * (T_LEN * 2) + 2 * t);
        xsf[t * BR + b] = v;
    }

    float c_state[7];
    #pragma unroll
    for (int q = 0; q < 7; q++) c_state[q] = 0.0f;

    __syncthreads();

    for (int t = 0; t < T_LEN; t++) {
        const float2* xrow = xsf + t * BR;

        // ---- phase 1: 2 gates x 14 batch rows per thread ----
        #pragma unroll
        for (int bb = 0; bb < HB; bb++) {
            const int b = bs + bb;
            const ulonglong2* hr = (const ulonglong2*)(hsm + b * H_DIM);
            unsigned long long a0a = pack2(0.0f, 0.0f);
            unsigned long long a0b = a0a, a1a = a0a, a1b = a0a;
            #pragma unroll
            for (int m = 0; m < H_DIM / 4; m++) {
                ulonglong2 hv = hr[m];  // h[4m..4m+3] as two f32x2
                a0a = fma2(hv.x, w0[2 * m + 0], a0a);
                a0b = fma2(hv.y, w0[2 * m + 1], a0b);
                a1a = fma2(hv.x, w1[2 * m + 0], a1a);
                a1b = fma2(hv.y, w1[2 * m + 1], a1b);
            }
            float2 xv = xrow[b];
            float l0, h0, l1, h1;
            unpack2(add2(a0a, a0b), l0, h0);
            unpack2(add2(a1a, a1b), l1, h1);
            float gv0 = bias0 + wA0 * xv.x + wA1 * xv.y + (l0 + h0);
            float gv1 = bias1 + wB0 * xv.x + wB1 * xv.y + (l1 + h1);
            *(float2*)(gsm + b * G_DIM + g0) = make_float2(gv0, gv1);
        }
        __syncthreads();

        // ---- phase 2: activations / state update, 7 (b,j) per thread ----
        #pragma unroll
        for (int q = 0; q < 7; q++) {
            int idx = tid + NTHR * q;
            int b = idx >> 6;
            int j = idx & 63;
            const float* gr = gsm + b * G_DIM + j;
            float gi = gr[0];
            float gf = gr[64];
            float gg = gr[128];
            float go = gr[192];
            float i_ = sigf(gi);
            float f_ = sigf(gf);
            float g_ = tanhf_(gg);
            float o_ = sigf(go);
            float c = f_ * c_state[q] + i_ * g_;
            c_state[q] = c;
            hsm[b * H_DIM + j] = o_ * tanhf_(c);
        }
        __syncthreads();
    }

    // ---- final projection: out[b] = dot(h_last, W_fc) + b_fc ----
    if (tid < H_DIM) gsm[tid] = wfc;   // stage W_fc into smem once
    __syncthreads();
    if (tid < BR) {
        int gb = base + tid;
        if (gb < B_TOT) {
            float acc = 0.0f;
            #pragma unroll
            for (int j = 0; j < H_DIM; j++)
                acc += hsm[tid * H_DIM + j] * gsm[j];
            out[gb] = acc + bfc;
        }
    }
}

extern "C" void kernel_launch(void* const* d_in, const int* in_sizes, int n_in,
                              void* d_out, int out_size) {
    const float* x    = (const float*)d_in[0];
    const float* W_ih = (const float*)d_in[1];
    const float* W_hh = (const float*)d_in[2];
    const float* b_ih = (const float*)d_in[3];
    const float* b_hh = (const float*)d_in[4];
    const float* W_fc = (const float*)d_in[5];
    const float* b_fc = (const float*)d_in[6];
    float* out = (float*)d_out;

    cudaFuncSetAttribute(lstm_kernel,
                         cudaFuncAttributeMaxDynamicSharedMemorySize,
                         SMEM_BYTES);

    int grid = (B_TOT + BR - 1) / BR;  // 147
    lstm_kernel<<<grid, NTHR, SMEM_BYTES>>>(x, W_ih, W_hh, b_ih, b_hh,
                                            W_fc, b_fc, out);
}